// round 3
// baseline (speedup 1.0000x reference)
#include <cuda_runtime.h>

#define KCTX 64
#define DIM  128
#define CAND 256
#define DSLEN 200
#define EPS 1e-8f
#define PITCH 132   // smem row pitch in floats; conflict-free for LDS.128 8-lane phases
#define NTHR 512

__device__ float g_A[KCTX * DIM];
__device__ float g_AM[KCTX * DIM];

// ---- index dtype sniffing: reference claims int64 but JAX w/o x64 emits int32 ----
__device__ __forceinline__ bool idx_is64(const void* p, long long V) {
    const long long* q = (const long long*)p;
    bool ok = true;
#pragma unroll
    for (int i = 0; i < 8; i++) {
        long long v = q[i];
        if (v < 0 || v >= V) ok = false;
    }
    return ok;
}
__device__ __forceinline__ long long load_idx(const void* p, long long i, bool is64) {
    return is64 ? ((const long long*)p)[i] : (long long)((const int*)p)[i];
}

// fast tanh via MUFU.EX2; abs err ~1e-6 (budget is 1e-3)
__device__ __forceinline__ float fast_tanh(float x) {
    return 1.f - 2.f / (1.f + __expf(2.f * x));
}

// -------- prep: A = table[t1_ctx]; AM = A @ att_mat --------
__global__ __launch_bounds__(DIM) void prep_kernel(
    const float* __restrict__ table,
    const float* __restrict__ att_mat,
    const void* __restrict__ t1_ctx,
    long long V)
{
    __shared__ float sa[DIM];
    const bool is64 = idx_is64(t1_ctx, V);
    int k = blockIdx.x;
    int j = threadIdx.x;
    long long row = load_idx(t1_ctx, k, is64);
    float a = table[row * DIM + j];
    g_A[k * DIM + j] = a;
    sa[j] = a;
    __syncthreads();
    float acc = 0.f;
#pragma unroll 8
    for (int d = 0; d < DIM; ++d)
        acc = fmaf(sa[d], att_mat[d * DIM + j], acc);
    g_AM[k * DIM + j] = acc;
}

// -------- main: one CTA per candidate, 512 threads --------
__global__ __launch_bounds__(NTHR) void cand_kernel(
    const float* __restrict__ table,
    const float* __restrict__ str_t1,
    const float* __restrict__ str_t2s,
    const float* __restrict__ W_bi,
    const float* __restrict__ b_bi,
    const void* __restrict__ t2_ctx,
    float* __restrict__ out,
    long long V)
{
    extern __shared__ float smem[];
    float* sAM = smem;                    // KCTX * PITCH (reused as sA after GEMM)
    float* sB  = smem + KCTX * PITCH;     // KCTX * PITCH

    __shared__ float rowsum[KCTX];
    __shared__ float colsum[KCTX];
    __shared__ float rows_w[KCTX];
    __shared__ float cols_w[KCTX];
    __shared__ float newA[DIM];
    __shared__ float newB[DIM];
    __shared__ float tvec[DIM];
    __shared__ float part[4][DIM];
    __shared__ float red3[3][16];
    __shared__ float s_con, s_str;

    const int tid = threadIdx.x;
    const int c   = blockIdx.x;
    const bool is64 = idx_is64(t2_ctx, V);

    // load AM (contiguous 32KB, L2-hot) into padded smem
    for (int i = tid; i < KCTX * DIM; i += NTHR) {
        int k = i >> 7, d = i & 127;
        sAM[k * PITCH + d] = g_AM[i];
    }
    // gather B rows via float4
    {
        const long long base = (long long)c * KCTX;
        for (int i = tid; i < KCTX * (DIM / 4); i += NTHR) {
            int k = i >> 5, q = i & 31;
            long long r = load_idx(t2_ctx, base + k, is64);
            float4 v = ((const float4*)(table + r * DIM))[q];
            float* dst = &sB[k * PITCH + q * 4];
            dst[0] = v.x; dst[1] = v.y; dst[2] = v.z; dst[3] = v.w;
        }
    }
    if (tid < KCTX) colsum[tid] = 0.f;
    __syncthreads();

    // ---- 64x64x128 GEMM, 2x4 per thread; rows = ty+32i, cols = tx+16j ----
    const int tx = tid & 15;
    const int ty = tid >> 4;   // 0..31
    float acc[2][4];
#pragma unroll
    for (int i = 0; i < 2; i++)
#pragma unroll
        for (int j = 0; j < 4; j++) acc[i][j] = 0.f;

#pragma unroll 4
    for (int d = 0; d < DIM; d += 4) {
        float4 av[2], bv[4];
#pragma unroll
        for (int i = 0; i < 2; i++)
            av[i] = *(const float4*)&sAM[(ty + 32 * i) * PITCH + d];
#pragma unroll
        for (int j = 0; j < 4; j++)
            bv[j] = *(const float4*)&sB[(tx + 16 * j) * PITCH + d];
#pragma unroll
        for (int i = 0; i < 2; i++)
#pragma unroll
            for (int j = 0; j < 4; j++) {
                acc[i][j] = fmaf(av[i].x, bv[j].x, acc[i][j]);
                acc[i][j] = fmaf(av[i].y, bv[j].y, acc[i][j]);
                acc[i][j] = fmaf(av[i].z, bv[j].z, acc[i][j]);
                acc[i][j] = fmaf(av[i].w, bv[j].w, acc[i][j]);
            }
    }

    // tanh + row/col partial sums (S never materialized)
    float pr[2] = {0.f, 0.f};
    float pc[4] = {0.f, 0.f, 0.f, 0.f};
#pragma unroll
    for (int i = 0; i < 2; i++)
#pragma unroll
        for (int j = 0; j < 4; j++) {
            float t = fast_tanh(acc[i][j]);
            pr[i] += t;
            pc[j] += t;
        }

    // row sums: reduce over tx within each 16-lane half-warp
#pragma unroll
    for (int i = 0; i < 2; i++) {
        float v = pr[i];
#pragma unroll
        for (int off = 1; off < 16; off <<= 1)
            v += __shfl_xor_sync(0xffffffffu, v, off);
        if (tx == 0) rowsum[ty + 32 * i] = v;
    }
    // col sums: combine the two ty's of this warp, then smem atomics across warps
#pragma unroll
    for (int j = 0; j < 4; j++) {
        float v = pc[j] + __shfl_xor_sync(0xffffffffu, pc[j], 16);
        if ((tid & 16) == 0)
            atomicAdd(&colsum[tx + 16 * j], v);
    }
    __syncthreads();

    // ---- softmaxes over k (length 64): warp 0 -> rows, warp 1 -> cols ----
    if (tid < 64) {
        const float* src = (tid < 32) ? rowsum : colsum;
        float* dst       = (tid < 32) ? rows_w : cols_w;
        int l = tid & 31;
        float v0 = src[l] * (1.f / 64.f);
        float v1 = src[l + 32] * (1.f / 64.f);
        float m = fmaxf(v0, v1);
#pragma unroll
        for (int off = 16; off > 0; off >>= 1)
            m = fmaxf(m, __shfl_xor_sync(0xffffffffu, m, off));
        float e0 = __expf(v0 - m), e1 = __expf(v1 - m);
        float s = e0 + e1;
#pragma unroll
        for (int off = 16; off > 0; off >>= 1)
            s += __shfl_xor_sync(0xffffffffu, s, off);
        float inv = 1.f / s;
        dst[l] = e0 * inv;
        dst[l + 32] = e1 * inv;
    }

    // ---- copy A into smem (sAM region now dead) for the new_A pass ----
    {
        float* sA = sAM;
        for (int i = tid; i < KCTX * (DIM / 4); i += NTHR) {
            float4 v = ((const float4*)g_A)[i];
            ((float4*)sA)[i] = v;
        }
    }

    // ---- string branch (all warps) ----
    {
        float p = 0.f, q1 = 0.f, q2 = 0.f;
        for (int i = tid; i < DSLEN; i += NTHR) {
            float x = str_t1[i];
            float y = str_t2s[c * DSLEN + i];
            p  = fmaf(x, y, p);
            q1 = fmaf(x, x, q1);
            q2 = fmaf(y, y, q2);
        }
#pragma unroll
        for (int off = 16; off > 0; off >>= 1) {
            p  += __shfl_xor_sync(0xffffffffu, p,  off);
            q1 += __shfl_xor_sync(0xffffffffu, q1, off);
            q2 += __shfl_xor_sync(0xffffffffu, q2, off);
        }
        int w = tid >> 5;
        if ((tid & 31) == 0) {
            red3[0][w] = p; red3[1][w] = q1; red3[2][w] = q2;
        }
    }
    __syncthreads();
    if (tid == 0) {
        float p = 0.f, q1 = 0.f, q2 = 0.f;
#pragma unroll
        for (int w = 0; w < 16; w++) { p += red3[0][w]; q1 += red3[1][w]; q2 += red3[2][w]; }
        float n1 = fmaxf(sqrtf(q1), EPS);
        float n2 = fmaxf(sqrtf(q2), EPS);
        s_str = p / (n1 * n2);
    }

    // ---- new_A = rows @ A (smem); new_B = cols . B (smem) ----
    if (tid < DIM) {
        const float* sA = sAM;
        float a = 0.f, b = 0.f;
#pragma unroll 8
        for (int k = 0; k < KCTX; k++) {
            a = fmaf(rows_w[k], sA[k * DIM + tid], a);
            b = fmaf(cols_w[k], sB[k * PITCH + tid], b);
        }
        newA[tid] = a;
        newB[tid] = b;
    }
    __syncthreads();

    // ---- bilinear: part[g][e] = sum_{d in slice g} newA[d] * W[d,e] ----
    {
        int e = tid & 127;
        int g = tid >> 7;          // 0..3, each covers 32 d's
        float t = 0.f;
#pragma unroll 8
        for (int d = 32 * g; d < 32 * g + 32; d++)
            t = fmaf(newA[d], W_bi[d * DIM + e], t);
        part[g][e] = t;
    }
    __syncthreads();
    if (tid < DIM)
        tvec[tid] = (part[0][tid] + part[1][tid] + part[2][tid] + part[3][tid]) * newB[tid];
    __syncthreads();
    if (tid < 32) {
        float v = tvec[tid] + tvec[tid + 32] + tvec[tid + 64] + tvec[tid + 96];
#pragma unroll
        for (int off = 16; off > 0; off >>= 1)
            v += __shfl_xor_sync(0xffffffffu, v, off);
        if (tid == 0) s_con = v + b_bi[0];
    }
    __syncthreads();

    if (tid == 0)
        out[c] = 0.5f * s_str + 0.5f * s_con;
}

extern "C" void kernel_launch(void* const* d_in, const int* in_sizes, int n_in,
                              void* d_out, int out_size)
{
    const float* table   = (const float*)d_in[0];
    const float* str_t1  = (const float*)d_in[1];
    const float* str_t2s = (const float*)d_in[2];
    const float* att_mat = (const float*)d_in[3];
    const float* W_bi    = (const float*)d_in[4];
    const float* b_bi    = (const float*)d_in[5];
    const void*  t1_ctx  = (const void*)d_in[6];
    const void*  t2_ctx  = (const void*)d_in[7];
    float* out = (float*)d_out;

    long long V = (long long)in_sizes[0] / DIM;

    cudaFuncSetAttribute(cand_kernel,
                         cudaFuncAttributeMaxDynamicSharedMemorySize,
                         2 * KCTX * PITCH * (int)sizeof(float));

    prep_kernel<<<KCTX, DIM>>>(table, att_mat, t1_ctx, V);
    cand_kernel<<<CAND, NTHR, 2 * KCTX * PITCH * (int)sizeof(float)>>>(
        table, str_t1, str_t2s, W_bi, b_bi, t2_ctx, out, V);
}

// round 5
// speedup vs baseline: 1.3324x; 1.3324x over previous
#include <cuda_runtime.h>
#include <cstdint>

#define KCTX 64
#define DIM  128
#define CAND 256
#define DSLEN 200
#define EPS 1e-8f
#define PITCH 132   // word pitch; 132 % 32 == 4 -> conflict-free frag access
#define NTHR 512

__device__ float    g_A[KCTX * DIM];
__device__ uint32_t g_AMt[KCTX * DIM];   // AM pre-converted to tf32 bits

// ---- index dtype sniffing: reference claims int64 but JAX w/o x64 emits int32 ----
__device__ __forceinline__ bool idx_is64(const void* p, long long V) {
    const long long* q = (const long long*)p;
    bool ok = true;
#pragma unroll
    for (int i = 0; i < 8; i++) {
        long long v = q[i];
        if (v < 0 || v >= V) ok = false;
    }
    return ok;
}
__device__ __forceinline__ long long load_idx(const void* p, long long i, bool is64) {
    return is64 ? ((const long long*)p)[i] : (long long)((const int*)p)[i];
}

__device__ __forceinline__ float fast_tanh(float x) {
    return 1.f - 2.f / (1.f + __expf(2.f * x));
}
__device__ __forceinline__ uint32_t f2tf32(float f) {
    uint32_t u;
    asm("cvt.rna.tf32.f32 %0, %1;" : "=r"(u) : "f"(f));
    return u;
}
__device__ __forceinline__ void mma_tf32(float c[4],
    uint32_t a0, uint32_t a1, uint32_t a2, uint32_t a3,
    uint32_t b0, uint32_t b1)
{
    asm volatile(
        "mma.sync.aligned.m16n8k8.row.col.f32.tf32.tf32.f32 "
        "{%0,%1,%2,%3}, {%4,%5,%6,%7}, {%8,%9}, {%0,%1,%2,%3};"
        : "+f"(c[0]), "+f"(c[1]), "+f"(c[2]), "+f"(c[3])
        : "r"(a0), "r"(a1), "r"(a2), "r"(a3), "r"(b0), "r"(b1));
}

// -------- prep: A = table[t1_ctx]; AM = A @ att_mat (fp32), stored as tf32 bits --------
__global__ __launch_bounds__(DIM) void prep_kernel(
    const float* __restrict__ table,
    const float* __restrict__ att_mat,
    const void* __restrict__ t1_ctx,
    long long V)
{
    __shared__ float sa[DIM];
    const bool is64 = idx_is64(t1_ctx, V);
    int k = blockIdx.x;
    int j = threadIdx.x;
    long long row = load_idx(t1_ctx, k, is64);
    float a = table[row * DIM + j];
    g_A[k * DIM + j] = a;
    sa[j] = a;
    __syncthreads();
    float acc = 0.f;
#pragma unroll 8
    for (int d = 0; d < DIM; ++d)
        acc = fmaf(sa[d], att_mat[d * DIM + j], acc);
    g_AMt[k * DIM + j] = f2tf32(acc);
}

// -------- main: one CTA per candidate, 512 threads, tf32 tensor-core GEMM --------
__global__ __launch_bounds__(NTHR) void cand_kernel(
    const float* __restrict__ table,
    const float* __restrict__ str_t1,
    const float* __restrict__ str_t2s,
    const float* __restrict__ W_bi,
    const float* __restrict__ b_bi,
    const void* __restrict__ t2_ctx,
    float* __restrict__ out,
    long long V)
{
    extern __shared__ uint32_t smem[];
    uint32_t* sAMt = smem;                       // [KCTX][PITCH] tf32 bits (reused as fp32 A later)
    uint32_t* sBt  = smem + KCTX * PITCH;        // [KCTX][PITCH] tf32 bits
    float*    sBf  = (float*)(smem + 2 * KCTX * PITCH); // [KCTX][PITCH] fp32 B

    __shared__ float rowsum[KCTX];
    __shared__ float colsum[KCTX];
    __shared__ float rows_w[KCTX];
    __shared__ float cols_w[KCTX];
    __shared__ float newA[DIM];
    __shared__ float newB[DIM];
    __shared__ float tvec[DIM];
    __shared__ float part[4][DIM];
    __shared__ float red3[3][16];
    __shared__ float s_con, s_str;

    const int tid = threadIdx.x;
    const int c   = blockIdx.x;
    const bool is64 = idx_is64(t2_ctx, V);

    // ---- fill: AM tf32 (L2-hot) + gathered B (fp32 copy + tf32 copy) ----
    for (int i = tid; i < KCTX * DIM; i += NTHR) {
        int k = i >> 7, d = i & 127;
        sAMt[k * PITCH + d] = g_AMt[i];
    }
    {
        const long long base = (long long)c * KCTX;
        for (int i = tid; i < KCTX * (DIM / 4); i += NTHR) {
            int k = i >> 5, q = i & 31;
            long long r = load_idx(t2_ctx, base + k, is64);
            float4 v = ((const float4*)(table + r * DIM))[q];
            float* fd = &sBf[k * PITCH + 4 * q];
            fd[0] = v.x; fd[1] = v.y; fd[2] = v.z; fd[3] = v.w;
            uint32_t* td = &sBt[k * PITCH + 4 * q];
            td[0] = f2tf32(v.x); td[1] = f2tf32(v.y);
            td[2] = f2tf32(v.z); td[3] = f2tf32(v.w);
        }
    }
    if (tid < KCTX) { rowsum[tid] = 0.f; colsum[tid] = 0.f; }
    __syncthreads();

    // ---- S = AM @ B^T via m16n8k8 tf32 mma; warp = m16 x n16 tile ----
    const int lane = tid & 31;
    const int wid  = tid >> 5;          // 0..15
    const int wm   = wid & 3;           // m-tile  (rows 16*wm..)
    const int wn   = wid >> 2;          // n-tile  (cols 16*wn..)
    const int g    = lane >> 2;         // groupID 0..7
    const int t4   = lane & 3;          // threadID_in_group

    float acc[2][4];
#pragma unroll
    for (int t = 0; t < 2; t++)
#pragma unroll
        for (int j = 0; j < 4; j++) acc[t][j] = 0.f;

    const uint32_t* aRow0 = &sAMt[(16 * wm + g) * PITCH];
    const uint32_t* aRow1 = &sAMt[(16 * wm + g + 8) * PITCH];
    const uint32_t* bRow0 = &sBt[(16 * wn + g) * PITCH];      // tile 0, n = 16wn+g
    const uint32_t* bRow1 = &sBt[(16 * wn + 8 + g) * PITCH];  // tile 1

#pragma unroll 4
    for (int kb = 0; kb < DIM; kb += 8) {
        uint32_t a0 = aRow0[kb + t4];
        uint32_t a1 = aRow1[kb + t4];
        uint32_t a2 = aRow0[kb + t4 + 4];
        uint32_t a3 = aRow1[kb + t4 + 4];
        uint32_t b0 = bRow0[kb + t4];
        uint32_t b1 = bRow0[kb + t4 + 4];
        mma_tf32(acc[0], a0, a1, a2, a3, b0, b1);
        uint32_t b2 = bRow1[kb + t4];
        uint32_t b3 = bRow1[kb + t4 + 4];
        mma_tf32(acc[1], a0, a1, a2, a3, b2, b3);
    }

    // ---- tanh + row/col sums from C fragments ----
    // C layout: c0=(row g, col 2t4), c1=(g, 2t4+1), c2=(g+8, 2t4), c3=(g+8, 2t4+1)
    float th[2][4];
#pragma unroll
    for (int t = 0; t < 2; t++)
#pragma unroll
        for (int j = 0; j < 4; j++) th[t][j] = fast_tanh(acc[t][j]);

    // row partials (sum over this thread's 4 cols), reduce within quad (same g)
    {
        float rlo = th[0][0] + th[0][1] + th[1][0] + th[1][1];
        float rhi = th[0][2] + th[0][3] + th[1][2] + th[1][3];
#pragma unroll
        for (int off = 1; off < 4; off <<= 1) {
            rlo += __shfl_xor_sync(0xffffffffu, rlo, off);
            rhi += __shfl_xor_sync(0xffffffffu, rhi, off);
        }
        if (t4 == 0) {
            atomicAdd(&rowsum[16 * wm + g],     rlo);
            atomicAdd(&rowsum[16 * wm + g + 8], rhi);
        }
    }
    // col partials (sum rows g and g+8), reduce across groups (xor 4,8,16)
    {
        float cp[2][2];
#pragma unroll
        for (int t = 0; t < 2; t++) {
            cp[t][0] = th[t][0] + th[t][2];
            cp[t][1] = th[t][1] + th[t][3];
#pragma unroll
            for (int off = 4; off < 32; off <<= 1) {
                cp[t][0] += __shfl_xor_sync(0xffffffffu, cp[t][0], off);
                cp[t][1] += __shfl_xor_sync(0xffffffffu, cp[t][1], off);
            }
        }
        if (g == 0) {
#pragma unroll
            for (int t = 0; t < 2; t++) {
                atomicAdd(&colsum[16 * wn + 8 * t + 2 * t4],     cp[t][0]);
                atomicAdd(&colsum[16 * wn + 8 * t + 2 * t4 + 1], cp[t][1]);
            }
        }
    }
    __syncthreads();

    // ---- softmaxes over k (length 64): warp 0 -> rows, warp 1 -> cols ----
    if (tid < 64) {
        const float* src = (tid < 32) ? rowsum : colsum;
        float* dst       = (tid < 32) ? rows_w : cols_w;
        int l = tid & 31;
        float v0 = src[l] * (1.f / 64.f);
        float v1 = src[l + 32] * (1.f / 64.f);
        float m = fmaxf(v0, v1);
#pragma unroll
        for (int off = 16; off > 0; off >>= 1)
            m = fmaxf(m, __shfl_xor_sync(0xffffffffu, m, off));
        float e0 = __expf(v0 - m), e1 = __expf(v1 - m);
        float s = e0 + e1;
#pragma unroll
        for (int off = 16; off > 0; off >>= 1)
            s += __shfl_xor_sync(0xffffffffu, s, off);
        float inv = 1.f / s;
        dst[l] = e0 * inv;
        dst[l + 32] = e1 * inv;
    }

    // ---- copy fp32 A into the (dead) sAMt region for new_A ----
    {
        float* sA = (float*)sAMt;
        for (int i = tid; i < KCTX * (DIM / 4); i += NTHR) {
            float4 v = ((const float4*)g_A)[i];
            ((float4*)sA)[i] = v;
        }
    }

    // ---- string branch (all warps) ----
    {
        float p = 0.f, q1 = 0.f, q2 = 0.f;
        for (int i = tid; i < DSLEN; i += NTHR) {
            float x = str_t1[i];
            float y = str_t2s[c * DSLEN + i];
            p  = fmaf(x, y, p);
            q1 = fmaf(x, x, q1);
            q2 = fmaf(y, y, q2);
        }
#pragma unroll
        for (int off = 16; off > 0; off >>= 1) {
            p  += __shfl_xor_sync(0xffffffffu, p,  off);
            q1 += __shfl_xor_sync(0xffffffffu, q1, off);
            q2 += __shfl_xor_sync(0xffffffffu, q2, off);
        }
        int w = tid >> 5;
        if ((tid & 31) == 0) {
            red3[0][w] = p; red3[1][w] = q1; red3[2][w] = q2;
        }
    }
    __syncthreads();
    if (tid == 0) {
        float p = 0.f, q1 = 0.f, q2 = 0.f;
#pragma unroll
        for (int w = 0; w < 16; w++) { p += red3[0][w]; q1 += red3[1][w]; q2 += red3[2][w]; }
        float n1 = fmaxf(sqrtf(q1), EPS);
        float n2 = fmaxf(sqrtf(q2), EPS);
        s_str = p / (n1 * n2);
    }

    // ---- new_A = rows @ A (fp32 smem); new_B = cols . B (fp32 smem) ----
    if (tid < DIM) {
        const float* sA = (const float*)sAMt;
        float a = 0.f, b = 0.f;
#pragma unroll 8
        for (int k = 0; k < KCTX; k++) {
            a = fmaf(rows_w[k], sA[k * DIM + tid], a);
            b = fmaf(cols_w[k], sBf[k * PITCH + tid], b);
        }
        newA[tid] = a;
        newB[tid] = b;
    }
    __syncthreads();

    // ---- bilinear: part[gg][e] = sum_{d in slice} newA[d] * W[d,e] ----
    {
        int e  = tid & 127;
        int gg = tid >> 7;          // 0..3, each covers 32 d's
        float t = 0.f;
#pragma unroll 8
        for (int d = 32 * gg; d < 32 * gg + 32; d++)
            t = fmaf(newA[d], W_bi[d * DIM + e], t);
        part[gg][e] = t;
    }
    __syncthreads();
    if (tid < DIM)
        tvec[tid] = (part[0][tid] + part[1][tid] + part[2][tid] + part[3][tid]) * newB[tid];
    __syncthreads();
    if (tid < 32) {
        float v = tvec[tid] + tvec[tid + 32] + tvec[tid + 64] + tvec[tid + 96];
#pragma unroll
        for (int off = 16; off > 0; off >>= 1)
            v += __shfl_xor_sync(0xffffffffu, v, off);
        if (tid == 0) s_con = v + b_bi[0];
    }
    __syncthreads();

    if (tid == 0)
        out[c] = 0.5f * s_str + 0.5f * s_con;
}

extern "C" void kernel_launch(void* const* d_in, const int* in_sizes, int n_in,
                              void* d_out, int out_size)
{
    const float* table   = (const float*)d_in[0];
    const float* str_t1  = (const float*)d_in[1];
    const float* str_t2s = (const float*)d_in[2];
    const float* att_mat = (const float*)d_in[3];
    const float* W_bi    = (const float*)d_in[4];
    const float* b_bi    = (const float*)d_in[5];
    const void*  t1_ctx  = (const void*)d_in[6];
    const void*  t2_ctx  = (const void*)d_in[7];
    float* out = (float*)d_out;

    long long V = (long long)in_sizes[0] / DIM;

    const int smem_bytes = 3 * KCTX * PITCH * (int)sizeof(uint32_t);
    cudaFuncSetAttribute(cand_kernel,
                         cudaFuncAttributeMaxDynamicSharedMemorySize,
                         smem_bytes);

    prep_kernel<<<KCTX, DIM>>>(table, att_mat, t1_ctx, V);
    cand_kernel<<<CAND, NTHR, smem_bytes>>>(
        table, str_t1, str_t2s, W_bi, b_bi, t2_ctx, out, V);
}

// round 8
// speedup vs baseline: 1.4630x; 1.0980x over previous
#include <cuda_runtime.h>
#include <cstdint>

#define KCTX 64
#define DIM  128
#define CAND 256
#define DSLEN 200
#define EPS 1e-8f
#define PITCH 132   // word pitch; 132 % 32 == 4 -> conflict-free frag access
#define NTHR 512

__device__ uint32_t g_AMt[KCTX * DIM];   // AM = A @ att_mat, tf32 bits
__device__ float    g_AW [KCTX * DIM];   // AW = A @ W_bi,   fp32

// ---- index dtype sniffing: reference claims int64 but JAX w/o x64 emits int32 ----
__device__ __forceinline__ bool idx_is64(const void* p, long long V) {
    const long long* q = (const long long*)p;
    bool ok = true;
#pragma unroll
    for (int i = 0; i < 8; i++) {
        long long v = q[i];
        if (v < 0 || v >= V) ok = false;
    }
    return ok;
}
__device__ __forceinline__ long long load_idx(const void* p, long long i, bool is64) {
    return is64 ? ((const long long*)p)[i] : (long long)((const int*)p)[i];
}

__device__ __forceinline__ float fast_tanh(float x) {
    return 1.f - 2.f / (1.f + __expf(2.f * x));
}
__device__ __forceinline__ uint32_t f2tf32(float f) {
    uint32_t u;
    asm("cvt.rna.tf32.f32 %0, %1;" : "=r"(u) : "f"(f));
    return u;
}
__device__ __forceinline__ void mma_tf32(float c[4],
    uint32_t a0, uint32_t a1, uint32_t a2, uint32_t a3,
    uint32_t b0, uint32_t b1)
{
    asm volatile(
        "mma.sync.aligned.m16n8k8.row.col.f32.tf32.tf32.f32 "
        "{%0,%1,%2,%3}, {%4,%5,%6,%7}, {%8,%9}, {%0,%1,%2,%3};"
        : "+f"(c[0]), "+f"(c[1]), "+f"(c[2]), "+f"(c[3])
        : "r"(a0), "r"(a1), "r"(a2), "r"(a3), "r"(b0), "r"(b1));
}

// -------- prep: blocks 0..63 -> AM row k (tf32); blocks 64..127 -> AW row k (fp32) --------
__global__ __launch_bounds__(DIM) void prep_kernel(
    const float* __restrict__ table,
    const float* __restrict__ att_mat,
    const float* __restrict__ W_bi,
    const void* __restrict__ t1_ctx,
    long long V)
{
    __shared__ float sa[DIM];
    const bool is64 = idx_is64(t1_ctx, V);
    const int b = blockIdx.x;
    const int k = b & (KCTX - 1);
    const int j = threadIdx.x;
    const float* M = (b < KCTX) ? att_mat : W_bi;

    long long row = load_idx(t1_ctx, k, is64);
    sa[j] = table[row * DIM + j];
    __syncthreads();
    float acc = 0.f;
#pragma unroll 8
    for (int d = 0; d < DIM; ++d)
        acc = fmaf(sa[d], M[d * DIM + j], acc);
    if (b < KCTX) g_AMt[k * DIM + j] = f2tf32(acc);
    else          g_AW [k * DIM + j] = acc;
}

// -------- main: one CTA per candidate, 512 threads --------
__global__ __launch_bounds__(NTHR) void cand_kernel(
    const float* __restrict__ table,
    const float* __restrict__ str_t1,
    const float* __restrict__ str_t2s,
    const float* __restrict__ b_bi,
    const void* __restrict__ t2_ctx,
    float* __restrict__ out,
    long long V)
{
    extern __shared__ uint32_t smem[];
    uint32_t* sAMt = smem;                               // [KCTX][PITCH] tf32
    uint32_t* sBt  = smem + KCTX * PITCH;                // [KCTX][PITCH] tf32
    float*    sBf  = (float*)(smem + 2 * KCTX * PITCH);  // [KCTX][PITCH] fp32

    __shared__ float rowsum[KCTX];
    __shared__ float colsum[KCTX];
    __shared__ float rows_w[KCTX];
    __shared__ float cols_w[KCTX];
    __shared__ float part[4][DIM];
    __shared__ float su[DIM];
    __shared__ float swk[KCTX];
    __shared__ float red3[3][16];
    __shared__ float s_str;

    const int tid  = threadIdx.x;
    const int c    = blockIdx.x;
    const int lane = tid & 31;
    const int wid  = tid >> 5;
    const bool is64 = idx_is64(t2_ctx, V);

    // ---- prefetch string branch into registers (overlaps fill-phase latency) ----
    float my_x = 0.f, my_y = 0.f;
    if (tid < DSLEN) {
        my_x = str_t1[tid];
        my_y = str_t2s[c * DSLEN + tid];
    }

    // ---- fill: gather B (fp32 + tf32) first (DRAM), then AM (L2-hot) ----
    {
        const long long base = (long long)c * KCTX;
        for (int i = tid; i < KCTX * (DIM / 4); i += NTHR) {
            int k = i >> 5, q = i & 31;
            long long r = load_idx(t2_ctx, base + k, is64);
            float4 v = ((const float4*)(table + r * DIM))[q];
            float* fd = &sBf[k * PITCH + 4 * q];
            fd[0] = v.x; fd[1] = v.y; fd[2] = v.z; fd[3] = v.w;
            uint32_t* td = &sBt[k * PITCH + 4 * q];
            td[0] = f2tf32(v.x); td[1] = f2tf32(v.y);
            td[2] = f2tf32(v.z); td[3] = f2tf32(v.w);
        }
    }
    for (int i = tid; i < KCTX * DIM; i += NTHR) {
        int k = i >> 7, d = i & 127;
        sAMt[k * PITCH + d] = g_AMt[i];
    }
    if (tid < KCTX) { rowsum[tid] = 0.f; colsum[tid] = 0.f; }
    __syncthreads();

    // ---- S = AM @ B^T via m16n8k8 tf32 mma; warp = m16 x n16 tile ----
    const int wm = wid & 3;
    const int wn = wid >> 2;
    const int g  = lane >> 2;
    const int t4 = lane & 3;

    float acc[2][4];
#pragma unroll
    for (int t = 0; t < 2; t++)
#pragma unroll
        for (int j = 0; j < 4; j++) acc[t][j] = 0.f;

    const uint32_t* aRow0 = &sAMt[(16 * wm + g) * PITCH];
    const uint32_t* aRow1 = &sAMt[(16 * wm + g + 8) * PITCH];
    const uint32_t* bRow0 = &sBt[(16 * wn + g) * PITCH];
    const uint32_t* bRow1 = &sBt[(16 * wn + 8 + g) * PITCH];

#pragma unroll 4
    for (int kb = 0; kb < DIM; kb += 8) {
        uint32_t a0 = aRow0[kb + t4];
        uint32_t a1 = aRow1[kb + t4];
        uint32_t a2 = aRow0[kb + t4 + 4];
        uint32_t a3 = aRow1[kb + t4 + 4];
        uint32_t b0 = bRow0[kb + t4];
        uint32_t b1 = bRow0[kb + t4 + 4];
        mma_tf32(acc[0], a0, a1, a2, a3, b0, b1);
        uint32_t b2 = bRow1[kb + t4];
        uint32_t b3 = bRow1[kb + t4 + 4];
        mma_tf32(acc[1], a0, a1, a2, a3, b2, b3);
    }

    // ---- tanh + row/col sums from C fragments ----
    float th[2][4];
#pragma unroll
    for (int t = 0; t < 2; t++)
#pragma unroll
        for (int j = 0; j < 4; j++) th[t][j] = fast_tanh(acc[t][j]);

    {
        float rlo = th[0][0] + th[0][1] + th[1][0] + th[1][1];
        float rhi = th[0][2] + th[0][3] + th[1][2] + th[1][3];
#pragma unroll
        for (int off = 1; off < 4; off <<= 1) {
            rlo += __shfl_xor_sync(0xffffffffu, rlo, off);
            rhi += __shfl_xor_sync(0xffffffffu, rhi, off);
        }
        if (t4 == 0) {
            atomicAdd(&rowsum[16 * wm + g],     rlo);
            atomicAdd(&rowsum[16 * wm + g + 8], rhi);
        }
    }
    {
        float cp[2][2];
#pragma unroll
        for (int t = 0; t < 2; t++) {
            cp[t][0] = th[t][0] + th[t][2];
            cp[t][1] = th[t][1] + th[t][3];
#pragma unroll
            for (int off = 4; off < 32; off <<= 1) {
                cp[t][0] += __shfl_xor_sync(0xffffffffu, cp[t][0], off);
                cp[t][1] += __shfl_xor_sync(0xffffffffu, cp[t][1], off);
            }
        }
        if (g == 0) {
#pragma unroll
            for (int t = 0; t < 2; t++) {
                atomicAdd(&colsum[16 * wn + 8 * t + 2 * t4],     cp[t][0]);
                atomicAdd(&colsum[16 * wn + 8 * t + 2 * t4 + 1], cp[t][1]);
            }
        }
    }
    __syncthreads();

    // ---- softmaxes (warps 0,1) + string partials (all warps, register data) ----
    if (tid < 64) {
        const float* src = (tid < 32) ? rowsum : colsum;
        float* dst       = (tid < 32) ? rows_w : cols_w;
        int l = tid & 31;
        float v0 = src[l] * (1.f / 64.f);
        float v1 = src[l + 32] * (1.f / 64.f);
        float m = fmaxf(v0, v1);
#pragma unroll
        for (int off = 16; off > 0; off >>= 1)
            m = fmaxf(m, __shfl_xor_sync(0xffffffffu, m, off));
        float e0 = __expf(v0 - m), e1 = __expf(v1 - m);
        float s = e0 + e1;
#pragma unroll
        for (int off = 16; off > 0; off >>= 1)
            s += __shfl_xor_sync(0xffffffffu, s, off);
        float inv = 1.f / s;
        dst[l] = e0 * inv;
        dst[l + 32] = e1 * inv;
    }
    {
        float p  = my_x * my_y;
        float q1 = my_x * my_x;
        float q2 = my_y * my_y;
#pragma unroll
        for (int off = 16; off > 0; off >>= 1) {
            p  += __shfl_xor_sync(0xffffffffu, p,  off);
            q1 += __shfl_xor_sync(0xffffffffu, q1, off);
            q2 += __shfl_xor_sync(0xffffffffu, q2, off);
        }
        if (lane == 0) { red3[0][wid] = p; red3[1][wid] = q1; red3[2][wid] = q2; }
    }
    __syncthreads();

    // ---- u-partials: part[gg][e] = sum_{k slice} rows_w[k] * AW[k,e]; tid0: s_str ----
    {
        int e  = tid & 127;
        int gg = tid >> 7;
        float t = 0.f;
#pragma unroll
        for (int k = 16 * gg; k < 16 * gg + 16; k++)
            t = fmaf(rows_w[k], g_AW[k * DIM + e], t);
        part[gg][e] = t;
    }
    if (tid == 0) {
        float p = 0.f, q1 = 0.f, q2 = 0.f;
#pragma unroll
        for (int w = 0; w < 7; w++) { p += red3[0][w]; q1 += red3[1][w]; q2 += red3[2][w]; }
        float n1 = fmaxf(sqrtf(q1), EPS);
        float n2 = fmaxf(sqrtf(q2), EPS);
        s_str = p / (n1 * n2);
    }
    __syncthreads();

    // ---- u combine ----
    if (tid < DIM)
        su[tid] = part[0][tid] + part[1][tid] + part[2][tid] + part[3][tid];
    __syncthreads();

    // ---- s_k = B_k . u, weighted by cols: warp handles 4 rows, lane = column ----
    {
#pragma unroll
        for (int r = 0; r < 4; r++) {
            int k = wid + 16 * r;
            const float* br = &sBf[k * PITCH];
            float v = fmaf(br[lane],      su[lane],
                      fmaf(br[lane + 32], su[lane + 32],
                      fmaf(br[lane + 64], su[lane + 64],
                           br[lane + 96] * su[lane + 96])));
#pragma unroll
            for (int off = 16; off > 0; off >>= 1)
                v += __shfl_xor_sync(0xffffffffu, v, off);
            if (lane == 0) swk[k] = v * cols_w[k];
        }
    }
    __syncthreads();

    // ---- final: warp 0 reduces swk, adds bias + string ----
    if (tid < 32) {
        float v = swk[tid] + swk[tid + 32];
#pragma unroll
        for (int off = 16; off > 0; off >>= 1)
            v += __shfl_xor_sync(0xffffffffu, v, off);
        if (tid == 0)
            out[c] = 0.5f * s_str + 0.5f * (v + b_bi[0]);
    }
}

extern "C" void kernel_launch(void* const* d_in, const int* in_sizes, int n_in,
                              void* d_out, int out_size)
{
    const float* table   = (const float*)d_in[0];
    const float* str_t1  = (const float*)d_in[1];
    const float* str_t2s = (const float*)d_in[2];
    const float* att_mat = (const float*)d_in[3];
    const float* W_bi    = (const float*)d_in[4];
    const float* b_bi    = (const float*)d_in[5];
    const void*  t1_ctx  = (const void*)d_in[6];
    const void*  t2_ctx  = (const void*)d_in[7];
    float* out = (float*)d_out;

    long long V = (long long)in_sizes[0] / DIM;

    const int smem_bytes = 3 * KCTX * PITCH * (int)sizeof(uint32_t);
    cudaFuncSetAttribute(cand_kernel,
                         cudaFuncAttributeMaxDynamicSharedMemorySize,
                         smem_bytes);

    prep_kernel<<<2 * KCTX, DIM>>>(table, att_mat, W_bi, t1_ctx, V);
    cand_kernel<<<CAND, NTHR, smem_bytes>>>(
        table, str_t1, str_t2s, b_bi, t2_ctx, out, V);
}